// round 9
// baseline (speedup 1.0000x reference)
#include <cuda_runtime.h>
#include <cuda_fp16.h>
#include <math.h>
#include <stdint.h>

// ---------------- problem constants ----------------
#define Bq   64
#define Dd   768
#define Nn   262144
#define Vv   50257
#define Kk   8
#define TEMP 10.0f
#define LAM  0.25f
#define EPSV 1e-10f

#define KPC    128                 // keys per CTA
#define NCHUNK (Nn / KPC)          // 2048
#define NKC    24                  // 768/32 d-tiles
#define TOPC   16                  // candidates rescored exactly

// smem layout (bytes)
#define KPITCH 80
#define KSTG   (KPC * KPITCH)      // 10240 per K stage (2 stages @ 0)
#define QPITCH 80
#define QSTG   (64 * QPITCH)       // 5120 per Q slot (3 slots)
#define SMO_QBUF 20480
#define SMO_K2   35840             // 128 floats (after q bufs)
#define SMEM_BYTES 36352
#define STP 132                    // sT pitch (floats); sT = 64 x 132 f32 @ 0 (aliases bufs)

// ---------------- scratch ----------------
__device__ float  g_cs[Bq * NCHUNK * Kk];
__device__ int    g_ci[Bq * NCHUNK * Kk];
__device__ float  g_w[Bq * Kk];
__device__ int    g_tok[Bq * Kk];
__device__ float  g_sumw[Bq];
__device__ float  g_pm[Bq * 4];
__device__ float  g_ps[Bq * 4];
__device__ __half g_qh[Bq * Dd];           // fp16 Q

// ---------------- helpers ----------------
__device__ __forceinline__ unsigned smem_u32(const void* p) {
    unsigned a;
    asm("{ .reg .u64 t; cvta.to.shared.u64 t, %1; cvt.u32.u64 %0, t; }" : "=r"(a) : "l"(p));
    return a;
}
__device__ __forceinline__ void cp16(unsigned dst, const void* src) {
    asm volatile("cp.async.cg.shared.global [%0], [%1], 16;" :: "r"(dst), "l"(src));
}
__device__ __forceinline__ void cp_commit() { asm volatile("cp.async.commit_group;" ::: "memory"); }
template<int N> __device__ __forceinline__ void cp_wait() { asm volatile("cp.async.wait_group %0;" :: "n"(N) : "memory"); }

__device__ __forceinline__ unsigned cvt_h2(float lo, float hi) {
    unsigned r;
    asm("cvt.rn.f16x2.f32 %0, %1, %2;" : "=r"(r) : "f"(hi), "f"(lo));
    return r;
}
__device__ __forceinline__ void ldm4(unsigned r[4], unsigned addr) {
    asm volatile("ldmatrix.sync.aligned.m8n8.x4.shared.b16 {%0,%1,%2,%3}, [%4];"
                 : "=r"(r[0]), "=r"(r[1]), "=r"(r[2]), "=r"(r[3]) : "r"(addr));
}
__device__ __forceinline__ void sts64(unsigned addr, unsigned w0, unsigned w1) {
    asm volatile("st.shared.v2.b32 [%0], {%1,%2};" :: "r"(addr), "r"(w0), "r"(w1));
}
__device__ __forceinline__ void mma_f16(float c[4],
                                        unsigned a0, unsigned a1, unsigned a2, unsigned a3,
                                        unsigned b0, unsigned b1) {
    asm volatile(
        "mma.sync.aligned.m16n8k16.row.col.f32.f16.f16.f32 "
        "{%0,%1,%2,%3}, {%4,%5,%6,%7}, {%8,%9}, {%0,%1,%2,%3};"
        : "+f"(c[0]), "+f"(c[1]), "+f"(c[2]), "+f"(c[3])
        : "r"(a0), "r"(a1), "r"(a2), "r"(a3), "r"(b0), "r"(b1));
}

// =====================================================================
// Kernel 0: Q fp32 -> fp16 global
// =====================================================================
__global__ __launch_bounds__(512)
void k_prepq(const float* __restrict__ qh) {
    int i = blockIdx.x * 512 + threadIdx.x;
    if (i < Bq * Dd) g_qh[i] = __float2half_rn(qh[i]);
}

// =====================================================================
// Kernel 1: fp16 MMA + ldmatrix. S[128 keys x 64 q] = K.Q^T - ||k||^2/2.
// 8 warps x 16 keys; K path: LDG fp32 -> exact k2 -> cvt fp16 -> STS.
// =====================================================================
__global__ void __launch_bounds__(256, 2)
k_scores_f16(const float* __restrict__ keys) {
    extern __shared__ char sm[];
    const unsigned smb = smem_u32(sm);
    float* k2s = (float*)(sm + SMO_K2);
    float* sT  = (float*)sm;                     // 64 x STP f32, post-mainloop

    const int tid = threadIdx.x;
    const int w = tid >> 5, lane = tid & 31;
    const int g = lane >> 2, t = lane & 3;
    const int kBase = blockIdx.x * KPC;

    // K-load role: thread owns 16B chunk jw of rows r0+32p (p<4)
    const int r0 = tid >> 3, jw = tid & 7;
    const float* kp0 = keys + (size_t)(kBase + r0) * Dd + jw * 4;

    // ldmatrix lane address bases
    const unsigned aRow = (lane & 7) + ((lane >> 3) & 1) * 8;
    const unsigned aCol = (lane >> 4) * 16;
    const unsigned aBase = smb + (w * 16 + aRow) * KPITCH + aCol;
    const unsigned bRow = lane & 7;
    const unsigned bNt  = (lane >> 4) & 1;
    const unsigned bKo  = ((lane >> 3) & 1) * 16;
    const unsigned bBase = smb + SMO_QBUF + (bNt * 8 + bRow) * QPITCH + bKo;

    float c[8][4];
    #pragma unroll
    for (int n = 0; n < 8; ++n)
        #pragma unroll
        for (int v = 0; v < 4; ++v) c[n][v] = 0.f;
    float k2a[4];
    #pragma unroll
    for (int p = 0; p < 4; ++p) k2a[p] = 0.f;

    // ---- prologue: Q slots 0,1 async; K tile 0 pack ----
    {
        int row = tid >> 2, ch = tid & 3;
        cp16(smb + SMO_QBUF + row * QPITCH + ch * 16, g_qh + row * Dd + ch * 8);
        cp_commit();
        cp16(smb + SMO_QBUF + QSTG + row * QPITCH + ch * 16, g_qh + row * Dd + 32 + ch * 8);
        cp_commit();
    }
    {
        float4 v[4];
        #pragma unroll
        for (int p = 0; p < 4; ++p) v[p] = *(const float4*)(kp0 + (size_t)p * 32 * Dd);
        #pragma unroll
        for (int p = 0; p < 4; ++p) {
            float4 x = v[p];
            k2a[p] = fmaf(x.x, x.x, k2a[p]); k2a[p] = fmaf(x.y, x.y, k2a[p]);
            k2a[p] = fmaf(x.z, x.z, k2a[p]); k2a[p] = fmaf(x.w, x.w, k2a[p]);
            sts64(smb + (r0 + 32 * p) * KPITCH + jw * 8,
                  cvt_h2(x.x, x.y), cvt_h2(x.z, x.w));
        }
    }
    cp_wait<1>();
    __syncthreads();

    // ---- mainloop ----
    for (int kc = 0; kc < NKC; ++kc) {
        const bool hasNext = (kc + 1 < NKC);

        // 1) LDG K(kc+1)
        float4 v[4];
        if (hasNext) {
            const float* kp = kp0 + (kc + 1) * 32;
            #pragma unroll
            for (int p = 0; p < 4; ++p) v[p] = *(const float4*)(kp + (size_t)p * 32 * Dd);
        }

        // 2) MMA(kc) via ldmatrix
        {
            const unsigned kst = aBase + (kc & 1) * KSTG;
            const unsigned qst = bBase + (kc % 3) * QSTG;
            #pragma unroll
            for (int ks = 0; ks < 2; ++ks) {
                unsigned A[4];
                ldm4(A, kst + ks * 32);
                #pragma unroll
                for (int np = 0; np < 4; ++np) {
                    unsigned B[4];
                    ldm4(B, qst + np * (16 * QPITCH) + ks * 32);
                    mma_f16(c[2 * np],     A[0], A[1], A[2], A[3], B[0], B[1]);
                    mma_f16(c[2 * np + 1], A[0], A[1], A[2], A[3], B[2], B[3]);
                }
            }
        }

        // 3) pack K(kc+1) -> stage (kc+1)&1, exact k2
        if (hasNext) {
            const unsigned kb = smb + ((kc + 1) & 1) * KSTG + jw * 8;
            #pragma unroll
            for (int p = 0; p < 4; ++p) {
                float4 x = v[p];
                k2a[p] = fmaf(x.x, x.x, k2a[p]); k2a[p] = fmaf(x.y, x.y, k2a[p]);
                k2a[p] = fmaf(x.z, x.z, k2a[p]); k2a[p] = fmaf(x.w, x.w, k2a[p]);
                sts64(kb + (r0 + 32 * p) * KPITCH, cvt_h2(x.x, x.y), cvt_h2(x.z, x.w));
            }
        }

        // 4) Q prefetch kc+2 into slot (kc+2)%3; ensure Q(kc+1) landed
        if (kc + 2 < NKC) {
            int row = tid >> 2, ch = tid & 3;
            cp16(smb + SMO_QBUF + ((kc + 2) % 3) * QSTG + row * QPITCH + ch * 16,
                 g_qh + row * Dd + (kc + 2) * 32 + ch * 8);
        }
        cp_commit();
        cp_wait<1>();
        __syncthreads();
    }
    cp_wait<0>();

    // ---- per-row k2 (reduce over 8 chunk-threads) ----
    #pragma unroll
    for (int p = 0; p < 4; ++p) {
        float s = k2a[p];
        #pragma unroll
        for (int off = 1; off < 8; off <<= 1) s += __shfl_xor_sync(0xffffffffu, s, off);
        if (jw == 0) k2s[r0 + 32 * p] = 0.5f * s;
    }
    __syncthreads();

    // ---- decode scores to sT[query][key] ----
    {
        const int k0 = w * 16 + g;
        const float h0 = k2s[k0], h1 = k2s[k0 + 8];
        #pragma unroll
        for (int n = 0; n < 8; ++n) {
            const int q0 = n * 8 + 2 * t;
            sT[q0 * STP + k0]           = c[n][0] - h0;
            sT[(q0 + 1) * STP + k0]     = c[n][1] - h0;
            sT[q0 * STP + k0 + 8]       = c[n][2] - h1;
            sT[(q0 + 1) * STP + k0 + 8] = c[n][3] - h1;
        }
    }
    __syncthreads();

    // ---- per-query top-8 (4 threads per query, 32 keys each) ----
    {
        const int q = tid >> 2, part = tid & 3;
        float lv[8]; int li[8];
        #pragma unroll
        for (int j = 0; j < 8; ++j) { lv[j] = -3.4e38f; li[j] = 0; }
        const float* row = sT + q * STP + part * 32;
        #pragma unroll 4
        for (int i = 0; i < 8; ++i) {
            float4 vv = *reinterpret_cast<const float4*>(row + i * 4);
            int bidx = kBase + part * 32 + i * 4;
            float vs[4] = {vv.x, vv.y, vv.z, vv.w};
            #pragma unroll
            for (int cc = 0; cc < 4; ++cc) {
                if (vs[cc] > lv[7]) {
                    lv[7] = vs[cc]; li[7] = bidx + cc;
                    #pragma unroll
                    for (int tt = 7; tt >= 1; --tt)
                        if (lv[tt] > lv[tt - 1]) {
                            float tv = lv[tt]; lv[tt] = lv[tt - 1]; lv[tt - 1] = tv;
                            int   ti = li[tt]; li[tt] = li[tt - 1]; li[tt - 1] = ti;
                        }
                }
            }
        }
        const int sl = lane & 3;
        for (int r = 0; r < Kk; ++r) {
            float mv = lv[0]; int mi = li[0]; int ml = sl;
            #pragma unroll
            for (int off = 1; off < 4; off <<= 1) {
                float ov = __shfl_xor_sync(0xffffffffu, mv, off);
                int   oi = __shfl_xor_sync(0xffffffffu, mi, off);
                int   ol = __shfl_xor_sync(0xffffffffu, ml, off);
                if (ov > mv || (ov == mv && ol < ml)) { mv = ov; mi = oi; ml = ol; }
            }
            if (ml == sl) {
                #pragma unroll
                for (int tt = 0; tt < 7; ++tt) { lv[tt] = lv[tt + 1]; li[tt] = li[tt + 1]; }
                lv[7] = -3.4e38f;
            }
            if (sl == 0) {
                size_t o = ((size_t)q * NCHUNK + blockIdx.x) * Kk + r;
                g_cs[o] = mv; g_ci[o] = mi;
            }
        }
    }
}

// =====================================================================
// Kernel 2: global approx top-16 -> exact fp32 rescore -> top-8
// =====================================================================
__global__ __launch_bounds__(256)
void k_topk(const float* __restrict__ qh, const float* __restrict__ keys,
            const void* __restrict__ values_raw) {
    __shared__ float sval[256 * 16];
    __shared__ int   sidx[256 * 16];
    __shared__ float rv[256];
    __shared__ int   rp[256];
    __shared__ int   topi[TOPC];
    __shared__ float exacts[TOPC];
    __shared__ int   is64;

    const int b = blockIdx.x, tid = threadIdx.x;

    if (tid == 0) is64 = 1;
    __syncthreads();
    {
        const int2* vv = (const int2*)values_raw;
        int bad = 0;
        #pragma unroll
        for (int s = 0; s < 16; ++s) bad |= vv[tid + s * 256].y;
        if (bad != 0) is64 = 0;
    }

    float lv[16]; int li[16];
    #pragma unroll
    for (int j = 0; j < 16; ++j) { lv[j] = -3.4e38f; li[j] = 0; }
    const size_t base = (size_t)b * (NCHUNK * Kk);
    for (int s = 0; s < (NCHUNK * Kk) / 256; ++s) {
        int j = tid + s * 256;
        float v = g_cs[base + j];
        int  ix = g_ci[base + j];
        if (v > lv[15]) {
            lv[15] = v; li[15] = ix;
            #pragma unroll
            for (int tt = 15; tt >= 1; --tt)
                if (lv[tt] > lv[tt - 1]) {
                    float tv = lv[tt]; lv[tt] = lv[tt - 1]; lv[tt - 1] = tv;
                    int   ti = li[tt]; li[tt] = li[tt - 1]; li[tt - 1] = ti;
                }
        }
    }
    #pragma unroll
    for (int j = 0; j < 16; ++j) { sval[tid * 16 + j] = lv[j]; sidx[tid * 16 + j] = li[j]; }
    __syncthreads();

    for (int r = 0; r < TOPC; ++r) {
        float best = -3.4e38f; int bp = 0;
        #pragma unroll
        for (int s = 0; s < 16; ++s) {
            int p = tid * 16 + s;
            if (sval[p] > best) { best = sval[p]; bp = p; }
        }
        rv[tid] = best; rp[tid] = bp;
        __syncthreads();
        for (int st = 128; st > 0; st >>= 1) {
            if (tid < st && rv[tid + st] > rv[tid]) { rv[tid] = rv[tid + st]; rp[tid] = rp[tid + st]; }
            __syncthreads();
        }
        if (tid == 0) { topi[r] = sidx[rp[0]]; sval[rp[0]] = -3.4e38f; }
        __syncthreads();
    }

    // exact fp32 rescore: 16 threads per candidate
    {
        int j = tid >> 4, l = tid & 15;
        const float* kr = keys + (size_t)topi[j] * Dd;
        const float* qr = qh + (size_t)b * Dd;
        float dot = 0.f, kk = 0.f;
        for (int d = l; d < Dd; d += 16) {
            float kv = kr[d];
            dot = fmaf(qr[d], kv, dot);
            kk  = fmaf(kv, kv, kk);
        }
        #pragma unroll
        for (int off = 8; off > 0; off >>= 1) {
            dot += __shfl_xor_sync(0xffffffffu, dot, off);
            kk  += __shfl_xor_sync(0xffffffffu, kk, off);
        }
        if (l == 0) exacts[j] = dot - 0.5f * kk;
    }
    __syncthreads();

    if (tid == 0) {
        int order[Kk]; unsigned used = 0;
        for (int r = 0; r < Kk; ++r) {
            float best = -3.4e38f; int bj = 0;
            for (int j = 0; j < TOPC; ++j)
                if (!((used >> j) & 1u) && exacts[j] > best) { best = exacts[j]; bj = j; }
            used |= 1u << bj; order[r] = bj;
        }
        float m = exacts[order[0]];
        float e[Kk], se = 0.f;
        for (int r = 0; r < Kk; ++r) { e[r] = expf(2.f * (exacts[order[r]] - m) / TEMP); se += e[r]; }
        float sw = 0.f;
        for (int r = 0; r < Kk; ++r) {
            float wv = e[r] / se;
            g_w[b * Kk + r] = wv; sw += wv;
            int gi = topi[order[r]];
            int tok = is64 ? (int)((const long long*)values_raw)[gi]
                           : ((const int*)values_raw)[gi];
            g_tok[b * Kk + r] = tok;
        }
        g_sumw[b] = sw;
    }
}

// =====================================================================
// Kernel 3a: per-(row, quarter) partial max & sum(exp); 256 blocks
// =====================================================================
__global__ __launch_bounds__(256)
void k_rowstats_part(const float* __restrict__ bl) {
    __shared__ float red[8];
    __shared__ float s_bc;
    const int b = blockIdx.x >> 2, p = blockIdx.x & 3;
    const int tid = threadIdx.x;
    const int wid = tid >> 5, lid = tid & 31;
    const size_t rowoff = (size_t)b * Vv;
    const float* row = bl + rowoff;
    const int vs = (p * Vv) / 4, ve = ((p + 1) * Vv) / 4;
    const int a0 = vs + (int)((4u - (unsigned)((rowoff + vs) & 3u)) & 3u);
    const int n4 = (ve - a0) >> 2;
    const float4* rowa = (const float4*)(row + a0);

    float m = -3.4e38f;
    for (int i = tid; i < n4; i += 256) {
        float4 v = rowa[i];
        m = fmaxf(m, fmaxf(fmaxf(v.x, v.y), fmaxf(v.z, v.w)));
    }
    if (vs + tid < a0) m = fmaxf(m, row[vs + tid]);
    for (int v = a0 + 4 * n4 + tid; v < ve; v += 256) m = fmaxf(m, row[v]);
    #pragma unroll
    for (int off = 16; off > 0; off >>= 1) m = fmaxf(m, __shfl_xor_sync(0xffffffffu, m, off));
    if (lid == 0) red[wid] = m;
    __syncthreads();
    if (tid < 8) {
        float x = red[tid];
        #pragma unroll
        for (int off = 4; off > 0; off >>= 1) x = fmaxf(x, __shfl_xor_sync(0xffu, x, off));
        if (tid == 0) { s_bc = x; g_pm[b * 4 + p] = x; }
    }
    __syncthreads();
    const float rm = s_bc;

    float s = 0.f;
    for (int i = tid; i < n4; i += 256) {
        float4 v = rowa[i];
        s += expf(v.x - rm) + expf(v.y - rm) + expf(v.z - rm) + expf(v.w - rm);
    }
    if (vs + tid < a0) s += expf(row[vs + tid] - rm);
    for (int v = a0 + 4 * n4 + tid; v < ve; v += 256) s += expf(row[v] - rm);
    #pragma unroll
    for (int off = 16; off > 0; off >>= 1) s += __shfl_xor_sync(0xffffffffu, s, off);
    if (lid == 0) red[wid] = s;
    __syncthreads();
    if (tid < 8) {
        float x = red[tid];
        #pragma unroll
        for (int off = 4; off > 0; off >>= 1) x += __shfl_xor_sync(0xffu, x, off);
        if (tid == 0) g_ps[b * 4 + p] = x;
    }
}

// =====================================================================
// Kernel 3b: final mix; alignment-peeled float4 (head/tail scalar)
// =====================================================================
__global__ __launch_bounds__(256)
void k_final(const float* __restrict__ bl, float* __restrict__ out, long long out_size) {
    __shared__ float ws[Kk]; __shared__ int ts[Kk];
    __shared__ float s_rm, s_rs, s_sw;
    const int b = blockIdx.y, tid = threadIdx.x;
    if (tid < Kk) { ws[tid] = g_w[b * Kk + tid]; ts[tid] = g_tok[b * Kk + tid]; }
    if (tid == 8)  s_sw = g_sumw[b];
    if (tid == 0) {
        float m0 = fmaxf(fmaxf(g_pm[b * 4], g_pm[b * 4 + 1]),
                         fmaxf(g_pm[b * 4 + 2], g_pm[b * 4 + 3]));
        float ss = 0.f;
        #pragma unroll
        for (int i = 0; i < 4; ++i) ss += g_ps[b * 4 + i] * expf(g_pm[b * 4 + i] - m0);
        s_rm = m0; s_rs = ss;
    }
    __syncthreads();

    const float rm = s_rm, rs = s_rs;
    const float Z = s_sw + (float)Vv * EPSV;
    const size_t BV = (size_t)Bq * Vv;
    const size_t rowoff = (size_t)b * Vv;
    const int mis = (int)((4u - ((unsigned)(rowoff & 3u))) & 3u);

    auto emit = [&](int v) {
        const size_t o = rowoff + v;
        float blv = bl[o];
        float tp = 0.f;
        #pragma unroll
        for (int j = 0; j < Kk; ++j) if (ts[j] == v) tp += ws[j];
        float pk = (tp + EPSV) / Z;
        float pb = expf(blv - rm) / rs;
        float pi = (1.0f - LAM) * pb + LAM * pk;
        if ((long long)o < out_size)            out[o]          = logf(pi);
        if ((long long)(BV + o) < out_size)     out[BV + o]     = blv;
        if ((long long)(2 * BV + o) < out_size) out[2 * BV + o] = logf(tp + EPSV);
    };

    const int v4 = mis + (blockIdx.x * 256 + tid) * 4;
    if (v4 + 4 <= Vv) {
        const size_t off = rowoff + v4;
        if ((long long)(2 * BV + off + 4) <= out_size) {
            float4 blv = *(const float4*)(bl + off);
            float tp[4] = {0.f, 0.f, 0.f, 0.f};
            #pragma unroll
            for (int j = 0; j < Kk; ++j) {
                int d = ts[j] - v4;
                if ((unsigned)d < 4u) tp[d] += ws[j];
            }
            float bv[4] = {blv.x, blv.y, blv.z, blv.w};
            float4 o1, o3;
            float* o1p = &o1.x; float* o3p = &o3.x;
            #pragma unroll
            for (int cidx = 0; cidx < 4; ++cidx) {
                float pk = (tp[cidx] + EPSV) / Z;
                float pb = expf(bv[cidx] - rm) / rs;
                o1p[cidx] = logf((1.0f - LAM) * pb + LAM * pk);
                o3p[cidx] = logf(tp[cidx] + EPSV);
            }
            *(float4*)(out + off)          = o1;
            *(float4*)(out + BV + off)     = blv;
            *(float4*)(out + 2 * BV + off) = o3;
        } else {
            #pragma unroll
            for (int cidx = 0; cidx < 4; ++cidx) emit(v4 + cidx);
        }
    } else {
        for (int v = v4; v < Vv; ++v) emit(v);
    }
    if (blockIdx.x == 0 && tid < mis) emit(tid);
}

// =====================================================================
extern "C" void kernel_launch(void* const* d_in, const int* in_sizes, int n_in,
                              void* d_out, int out_size) {
    const float* qh   = (const float*)d_in[0];   // [B, D] f32
    const float* bl   = (const float*)d_in[1];   // [B, V] f32
    const float* keys = (const float*)d_in[2];   // [N, D] f32
    const void*  vals = d_in[3];                 // [N] int64 (or int32)
    float* out = (float*)d_out;

    cudaFuncSetAttribute(k_scores_f16, cudaFuncAttributeMaxDynamicSharedMemorySize, SMEM_BYTES);

    k_prepq<<<(Bq * Dd + 511) / 512, 512>>>(qh);
    k_scores_f16<<<NCHUNK, 256, SMEM_BYTES>>>(keys);
    k_topk<<<Bq, 256>>>(qh, keys, vals);
    k_rowstats_part<<<Bq * 4, 256>>>(bl);
    dim3 g3((Vv / 4 + 256) / 256, Bq);
    k_final<<<g3, 256>>>(bl, out, (long long)out_size);
}

// round 10
// speedup vs baseline: 1.1617x; 1.1617x over previous
#include <cuda_runtime.h>
#include <cuda_fp16.h>
#include <math.h>
#include <stdint.h>

// ---------------- problem constants ----------------
#define Bq   64
#define Dd   768
#define Nn   262144
#define Vv   50257
#define Kk   8
#define TEMP 10.0f
#define LAM  0.25f
#define EPSV 1e-10f

#define KPC    256                 // keys per CTA
#define NCHUNK (Nn / KPC)          // 1024
#define NKC    24                  // 768/32 d-tiles
#define TOPC   16                  // candidates rescored exactly

// smem layout (bytes)
#define KPITCH 80
#define KSTG   (KPC * KPITCH)      // 20480 per K stage (2 stages @ 0)
#define QPITCH 80
#define QSTG   (64 * QPITCH)       // 5120 per Q slot (3 slots)
#define SMO_QBUF 40960
#define SMO_K2   67584             // after sT region (sT = 64 x 264 f32 @ 0, aliases bufs)
#define SMEM_BYTES 68608

// ---------------- scratch ----------------
__device__ float  g_cs[Bq * NCHUNK * Kk];
__device__ int    g_ci[Bq * NCHUNK * Kk];
__device__ float  g_w[Bq * Kk];
__device__ int    g_tok[Bq * Kk];
__device__ float  g_sumw[Bq];
__device__ float  g_pm[Bq * 4];
__device__ float  g_ps[Bq * 4];
__device__ __half g_qh[Bq * Dd];           // fp16 Q

// ---------------- helpers ----------------
__device__ __forceinline__ unsigned smem_u32(const void* p) {
    unsigned a;
    asm("{ .reg .u64 t; cvta.to.shared.u64 t, %1; cvt.u32.u64 %0, t; }" : "=r"(a) : "l"(p));
    return a;
}
__device__ __forceinline__ void cp16(unsigned dst, const void* src) {
    asm volatile("cp.async.cg.shared.global [%0], [%1], 16;" :: "r"(dst), "l"(src));
}
__device__ __forceinline__ void cp_commit() { asm volatile("cp.async.commit_group;" ::: "memory"); }
template<int N> __device__ __forceinline__ void cp_wait() { asm volatile("cp.async.wait_group %0;" :: "n"(N) : "memory"); }

__device__ __forceinline__ unsigned cvt_h2(float lo, float hi) {
    unsigned r;
    asm("cvt.rn.f16x2.f32 %0, %1, %2;" : "=r"(r) : "f"(hi), "f"(lo));
    return r;
}
__device__ __forceinline__ void ldm4(unsigned r[4], unsigned addr) {
    asm volatile("ldmatrix.sync.aligned.m8n8.x4.shared.b16 {%0,%1,%2,%3}, [%4];"
                 : "=r"(r[0]), "=r"(r[1]), "=r"(r[2]), "=r"(r[3]) : "r"(addr));
}
__device__ __forceinline__ void sts64(unsigned addr, unsigned w0, unsigned w1) {
    asm volatile("st.shared.v2.b32 [%0], {%1,%2};" :: "r"(addr), "r"(w0), "r"(w1));
}
__device__ __forceinline__ void mma_f16(float c[4],
                                        unsigned a0, unsigned a1, unsigned a2, unsigned a3,
                                        unsigned b0, unsigned b1) {
    asm volatile(
        "mma.sync.aligned.m16n8k16.row.col.f32.f16.f16.f32 "
        "{%0,%1,%2,%3}, {%4,%5,%6,%7}, {%8,%9}, {%0,%1,%2,%3};"
        : "+f"(c[0]), "+f"(c[1]), "+f"(c[2]), "+f"(c[3])
        : "r"(a0), "r"(a1), "r"(a2), "r"(a3), "r"(b0), "r"(b1));
}

// =====================================================================
// Dummy kernel (aligns ncu capture slot onto k_scores)
// =====================================================================
__global__ void k_dummy() {}

// =====================================================================
// Kernel 0: Q fp32 -> fp16 global
// =====================================================================
__global__ __launch_bounds__(512)
void k_prepq(const float* __restrict__ qh) {
    int i = blockIdx.x * 512 + threadIdx.x;
    if (i < Bq * Dd) g_qh[i] = __float2half_rn(qh[i]);
}

// =====================================================================
// Kernel 1: fp16 MMA + ldmatrix. S[256 keys x 64 q] = K.Q^T - ||k||^2/2.
// =====================================================================
__global__ void __launch_bounds__(256, 2)
k_scores_f16(const float* __restrict__ keys) {
    extern __shared__ char sm[];
    const unsigned smb = smem_u32(sm);
    float* k2s = (float*)(sm + SMO_K2);
    float* sT  = (float*)sm;                     // 64 x 264 f32, post-mainloop

    const int tid = threadIdx.x;
    const int w = tid >> 5, lane = tid & 31;
    const int g = lane >> 2, t = lane & 3;
    const int kBase = blockIdx.x * KPC;

    // K-load role: thread owns 16B chunk jw of rows r0+32p
    const int r0 = tid >> 3, jw = tid & 7;
    const float* kp0 = keys + (size_t)(kBase + r0) * Dd + jw * 4;

    // ldmatrix lane address bases
    const unsigned aRow = (lane & 7) + ((lane >> 3) & 1) * 8;
    const unsigned aCol = (lane >> 4) * 16;
    const unsigned aBase = smb + (w * 32 + aRow) * KPITCH + aCol;
    const unsigned bRow = lane & 7;
    const unsigned bNt  = (lane >> 4) & 1;
    const unsigned bKo  = ((lane >> 3) & 1) * 16;
    const unsigned bBase = smb + SMO_QBUF + (bNt * 8 + bRow) * QPITCH + bKo;

    float c[2][8][4];
    #pragma unroll
    for (int m = 0; m < 2; ++m)
        #pragma unroll
        for (int n = 0; n < 8; ++n)
            #pragma unroll
            for (int v = 0; v < 4; ++v) c[m][n][v] = 0.f;
    float k2a[8];
    #pragma unroll
    for (int p = 0; p < 8; ++p) k2a[p] = 0.f;

    // ---- prologue: Q slots 0,1 async; K tile 0 pack ----
    {
        int row = tid >> 2, ch = tid & 3;
        cp16(smb + SMO_QBUF + row * QPITCH + ch * 16, g_qh + row * Dd + ch * 8);
        cp_commit();
        cp16(smb + SMO_QBUF + QSTG + row * QPITCH + ch * 16, g_qh + row * Dd + 32 + ch * 8);
        cp_commit();
    }
    {
        float4 v[8];
        #pragma unroll
        for (int p = 0; p < 8; ++p) v[p] = *(const float4*)(kp0 + (size_t)p * 32 * Dd);
        #pragma unroll
        for (int p = 0; p < 8; ++p) {
            float4 x = v[p];
            k2a[p] = fmaf(x.x, x.x, k2a[p]); k2a[p] = fmaf(x.y, x.y, k2a[p]);
            k2a[p] = fmaf(x.z, x.z, k2a[p]); k2a[p] = fmaf(x.w, x.w, k2a[p]);
            sts64(smb + (r0 + 32 * p) * KPITCH + jw * 8,
                  cvt_h2(x.x, x.y), cvt_h2(x.z, x.w));
        }
    }
    cp_wait<1>();
    __syncthreads();

    // ---- mainloop ----
    for (int kc = 0; kc < NKC; ++kc) {
        const bool hasNext = (kc + 1 < NKC);

        // 1) LDG K(kc+1)
        float4 v[8];
        if (hasNext) {
            const float* kp = kp0 + (kc + 1) * 32;
            #pragma unroll
            for (int p = 0; p < 8; ++p) v[p] = *(const float4*)(kp + (size_t)p * 32 * Dd);
        }

        // 2) MMA(kc) via ldmatrix
        {
            const unsigned kst = aBase + (kc & 1) * KSTG;
            const unsigned qst = bBase + (kc % 3) * QSTG;
            #pragma unroll
            for (int ks = 0; ks < 2; ++ks) {
                unsigned A0[4], A1[4];
                ldm4(A0, kst + ks * 32);
                ldm4(A1, kst + 16 * KPITCH + ks * 32);
                #pragma unroll
                for (int np = 0; np < 4; ++np) {
                    unsigned B[4];
                    ldm4(B, qst + np * (16 * QPITCH) + ks * 32);
                    mma_f16(c[0][2 * np],     A0[0], A0[1], A0[2], A0[3], B[0], B[1]);
                    mma_f16(c[0][2 * np + 1], A0[0], A0[1], A0[2], A0[3], B[2], B[3]);
                    mma_f16(c[1][2 * np],     A1[0], A1[1], A1[2], A1[3], B[0], B[1]);
                    mma_f16(c[1][2 * np + 1], A1[0], A1[1], A1[2], A1[3], B[2], B[3]);
                }
            }
        }

        // 3) pack K(kc+1) -> stage (kc+1)&1, exact k2
        if (hasNext) {
            const unsigned kb = smb + ((kc + 1) & 1) * KSTG + jw * 8;
            #pragma unroll
            for (int p = 0; p < 8; ++p) {
                float4 x = v[p];
                k2a[p] = fmaf(x.x, x.x, k2a[p]); k2a[p] = fmaf(x.y, x.y, k2a[p]);
                k2a[p] = fmaf(x.z, x.z, k2a[p]); k2a[p] = fmaf(x.w, x.w, k2a[p]);
                sts64(kb + (r0 + 32 * p) * KPITCH, cvt_h2(x.x, x.y), cvt_h2(x.z, x.w));
            }
        }

        // 4) Q prefetch kc+2 into slot (kc+2)%3; ensure Q(kc+1) landed
        if (kc + 2 < NKC) {
            int row = tid >> 2, ch = tid & 3;
            cp16(smb + SMO_QBUF + ((kc + 2) % 3) * QSTG + row * QPITCH + ch * 16,
                 g_qh + row * Dd + (kc + 2) * 32 + ch * 8);
        }
        cp_commit();
        cp_wait<1>();
        __syncthreads();
    }
    cp_wait<0>();

    // ---- per-row k2 (reduce over 8 chunk-threads) ----
    #pragma unroll
    for (int p = 0; p < 8; ++p) {
        float s = k2a[p];
        #pragma unroll
        for (int off = 1; off < 8; off <<= 1) s += __shfl_xor_sync(0xffffffffu, s, off);
        if (jw == 0) k2s[r0 + 32 * p] = 0.5f * s;
    }
    __syncthreads();

    // ---- decode scores to sT[query][key] ----
    #pragma unroll
    for (int m = 0; m < 2; ++m) {
        const int k0 = w * 32 + m * 16 + g;
        const float h0 = k2s[k0], h1 = k2s[k0 + 8];
        #pragma unroll
        for (int n = 0; n < 8; ++n) {
            const int q0 = n * 8 + 2 * t;
            sT[q0 * 264 + k0]           = c[m][n][0] - h0;
            sT[(q0 + 1) * 264 + k0]     = c[m][n][1] - h0;
            sT[q0 * 264 + k0 + 8]       = c[m][n][2] - h1;
            sT[(q0 + 1) * 264 + k0 + 8] = c[m][n][3] - h1;
        }
    }
    __syncthreads();

    // ---- per-query top-8 (4 threads per query) ----
    {
        const int q = tid >> 2, part = tid & 3;
        float lv[8]; int li[8];
        #pragma unroll
        for (int j = 0; j < 8; ++j) { lv[j] = -3.4e38f; li[j] = 0; }
        const float* row = sT + q * 264 + part * 64;
        #pragma unroll 4
        for (int i = 0; i < 16; ++i) {
            float4 vv = *reinterpret_cast<const float4*>(row + i * 4);
            int bidx = kBase + part * 64 + i * 4;
            float vs[4] = {vv.x, vv.y, vv.z, vv.w};
            #pragma unroll
            for (int cc = 0; cc < 4; ++cc) {
                if (vs[cc] > lv[7]) {
                    lv[7] = vs[cc]; li[7] = bidx + cc;
                    #pragma unroll
                    for (int tt = 7; tt >= 1; --tt)
                        if (lv[tt] > lv[tt - 1]) {
                            float tv = lv[tt]; lv[tt] = lv[tt - 1]; lv[tt - 1] = tv;
                            int   ti = li[tt]; li[tt] = li[tt - 1]; li[tt - 1] = ti;
                        }
                }
            }
        }
        const int sl = lane & 3;
        for (int r = 0; r < Kk; ++r) {
            float mv = lv[0]; int mi = li[0]; int ml = sl;
            #pragma unroll
            for (int off = 1; off < 4; off <<= 1) {
                float ov = __shfl_xor_sync(0xffffffffu, mv, off);
                int   oi = __shfl_xor_sync(0xffffffffu, mi, off);
                int   ol = __shfl_xor_sync(0xffffffffu, ml, off);
                if (ov > mv || (ov == mv && ol < ml)) { mv = ov; mi = oi; ml = ol; }
            }
            if (ml == sl) {
                #pragma unroll
                for (int tt = 0; tt < 7; ++tt) { lv[tt] = lv[tt + 1]; li[tt] = li[tt + 1]; }
                lv[7] = -3.4e38f;
            }
            if (sl == 0) {
                size_t o = ((size_t)q * NCHUNK + blockIdx.x) * Kk + r;
                g_cs[o] = mv; g_ci[o] = mi;
            }
        }
    }
}

// =====================================================================
// Kernel 2: global approx top-16 -> exact fp32 rescore -> top-8
// =====================================================================
__global__ __launch_bounds__(256)
void k_topk(const float* __restrict__ qh, const float* __restrict__ keys,
            const void* __restrict__ values_raw) {
    __shared__ float sval[256 * 16];
    __shared__ int   sidx[256 * 16];
    __shared__ float rv[256];
    __shared__ int   rp[256];
    __shared__ int   topi[TOPC];
    __shared__ float exacts[TOPC];
    __shared__ int   is64;

    const int b = blockIdx.x, tid = threadIdx.x;

    if (tid == 0) is64 = 1;
    __syncthreads();
    {
        const int2* vv = (const int2*)values_raw;
        int bad = 0;
        #pragma unroll
        for (int s = 0; s < 16; ++s) bad |= vv[tid + s * 256].y;
        if (bad != 0) is64 = 0;
    }

    float lv[16]; int li[16];
    #pragma unroll
    for (int j = 0; j < 16; ++j) { lv[j] = -3.4e38f; li[j] = 0; }
    const size_t base = (size_t)b * (NCHUNK * Kk);
    for (int s = 0; s < (NCHUNK * Kk) / 256; ++s) {
        int j = tid + s * 256;
        float v = g_cs[base + j];
        int  ix = g_ci[base + j];
        if (v > lv[15]) {
            lv[15] = v; li[15] = ix;
            #pragma unroll
            for (int tt = 15; tt >= 1; --tt)
                if (lv[tt] > lv[tt - 1]) {
                    float tv = lv[tt]; lv[tt] = lv[tt - 1]; lv[tt - 1] = tv;
                    int   ti = li[tt]; li[tt] = li[tt - 1]; li[tt - 1] = ti;
                }
        }
    }
    #pragma unroll
    for (int j = 0; j < 16; ++j) { sval[tid * 16 + j] = lv[j]; sidx[tid * 16 + j] = li[j]; }
    __syncthreads();

    for (int r = 0; r < TOPC; ++r) {
        float best = -3.4e38f; int bp = 0;
        #pragma unroll
        for (int s = 0; s < 16; ++s) {
            int p = tid * 16 + s;
            if (sval[p] > best) { best = sval[p]; bp = p; }
        }
        rv[tid] = best; rp[tid] = bp;
        __syncthreads();
        for (int st = 128; st > 0; st >>= 1) {
            if (tid < st && rv[tid + st] > rv[tid]) { rv[tid] = rv[tid + st]; rp[tid] = rp[tid + st]; }
            __syncthreads();
        }
        if (tid == 0) { topi[r] = sidx[rp[0]]; sval[rp[0]] = -3.4e38f; }
        __syncthreads();
    }

    // exact fp32 rescore: 16 threads per candidate
    {
        int j = tid >> 4, l = tid & 15;
        const float* kr = keys + (size_t)topi[j] * Dd;
        const float* qr = qh + (size_t)b * Dd;
        float dot = 0.f, kk = 0.f;
        for (int d = l; d < Dd; d += 16) {
            float kv = kr[d];
            dot = fmaf(qr[d], kv, dot);
            kk  = fmaf(kv, kv, kk);
        }
        #pragma unroll
        for (int off = 8; off > 0; off >>= 1) {
            dot += __shfl_xor_sync(0xffffffffu, dot, off);
            kk  += __shfl_xor_sync(0xffffffffu, kk, off);
        }
        if (l == 0) exacts[j] = dot - 0.5f * kk;
    }
    __syncthreads();

    if (tid == 0) {
        int order[Kk]; unsigned used = 0;
        for (int r = 0; r < Kk; ++r) {
            float best = -3.4e38f; int bj = 0;
            for (int j = 0; j < TOPC; ++j)
                if (!((used >> j) & 1u) && exacts[j] > best) { best = exacts[j]; bj = j; }
            used |= 1u << bj; order[r] = bj;
        }
        float m = exacts[order[0]];
        float e[Kk], se = 0.f;
        for (int r = 0; r < Kk; ++r) { e[r] = expf(2.f * (exacts[order[r]] - m) / TEMP); se += e[r]; }
        float sw = 0.f;
        for (int r = 0; r < Kk; ++r) {
            float wv = e[r] / se;
            g_w[b * Kk + r] = wv; sw += wv;
            int gi = topi[order[r]];
            int tok = is64 ? (int)((const long long*)values_raw)[gi]
                           : ((const int*)values_raw)[gi];
            g_tok[b * Kk + r] = tok;
        }
        g_sumw[b] = sw;
    }
}

// =====================================================================
// Kernel 3a: per-(row, quarter) partial max & sum(exp); 256 blocks
// =====================================================================
__global__ __launch_bounds__(256)
void k_rowstats_part(const float* __restrict__ bl) {
    __shared__ float red[8];
    __shared__ float s_bc;
    const int b = blockIdx.x >> 2, p = blockIdx.x & 3;
    const int tid = threadIdx.x;
    const int wid = tid >> 5, lid = tid & 31;
    const size_t rowoff = (size_t)b * Vv;
    const float* row = bl + rowoff;
    const int vs = (p * Vv) / 4, ve = ((p + 1) * Vv) / 4;
    const int a0 = vs + (int)((4u - (unsigned)((rowoff + vs) & 3u)) & 3u);
    const int n4 = (ve - a0) >> 2;
    const float4* rowa = (const float4*)(row + a0);

    float m = -3.4e38f;
    for (int i = tid; i < n4; i += 256) {
        float4 v = rowa[i];
        m = fmaxf(m, fmaxf(fmaxf(v.x, v.y), fmaxf(v.z, v.w)));
    }
    if (vs + tid < a0) m = fmaxf(m, row[vs + tid]);
    for (int v = a0 + 4 * n4 + tid; v < ve; v += 256) m = fmaxf(m, row[v]);
    #pragma unroll
    for (int off = 16; off > 0; off >>= 1) m = fmaxf(m, __shfl_xor_sync(0xffffffffu, m, off));
    if (lid == 0) red[wid] = m;
    __syncthreads();
    if (tid < 8) {
        float x = red[tid];
        #pragma unroll
        for (int off = 4; off > 0; off >>= 1) x = fmaxf(x, __shfl_xor_sync(0xffu, x, off));
        if (tid == 0) { s_bc = x; g_pm[b * 4 + p] = x; }
    }
    __syncthreads();
    const float rm = s_bc;

    float s = 0.f;
    for (int i = tid; i < n4; i += 256) {
        float4 v = rowa[i];
        s += expf(v.x - rm) + expf(v.y - rm) + expf(v.z - rm) + expf(v.w - rm);
    }
    if (vs + tid < a0) s += expf(row[vs + tid] - rm);
    for (int v = a0 + 4 * n4 + tid; v < ve; v += 256) s += expf(row[v] - rm);
    #pragma unroll
    for (int off = 16; off > 0; off >>= 1) s += __shfl_xor_sync(0xffffffffu, s, off);
    if (lid == 0) red[wid] = s;
    __syncthreads();
    if (tid < 8) {
        float x = red[tid];
        #pragma unroll
        for (int off = 4; off > 0; off >>= 1) x += __shfl_xor_sync(0xffu, x, off);
        if (tid == 0) g_ps[b * 4 + p] = x;
    }
}

// =====================================================================
// Kernel 3b: final mix; alignment-peeled float4 (head/tail scalar)
// =====================================================================
__global__ __launch_bounds__(256)
void k_final(const float* __restrict__ bl, float* __restrict__ out, long long out_size) {
    __shared__ float ws[Kk]; __shared__ int ts[Kk];
    __shared__ float s_rm, s_rs, s_sw;
    const int b = blockIdx.y, tid = threadIdx.x;
    if (tid < Kk) { ws[tid] = g_w[b * Kk + tid]; ts[tid] = g_tok[b * Kk + tid]; }
    if (tid == 8)  s_sw = g_sumw[b];
    if (tid == 0) {
        float m0 = fmaxf(fmaxf(g_pm[b * 4], g_pm[b * 4 + 1]),
                         fmaxf(g_pm[b * 4 + 2], g_pm[b * 4 + 3]));
        float ss = 0.f;
        #pragma unroll
        for (int i = 0; i < 4; ++i) ss += g_ps[b * 4 + i] * expf(g_pm[b * 4 + i] - m0);
        s_rm = m0; s_rs = ss;
    }
    __syncthreads();

    const float rm = s_rm, rs = s_rs;
    const float Z = s_sw + (float)Vv * EPSV;
    const size_t BV = (size_t)Bq * Vv;
    const size_t rowoff = (size_t)b * Vv;
    const int mis = (int)((4u - ((unsigned)(rowoff & 3u))) & 3u);

    auto emit = [&](int v) {
        const size_t o = rowoff + v;
        float blv = bl[o];
        float tp = 0.f;
        #pragma unroll
        for (int j = 0; j < Kk; ++j) if (ts[j] == v) tp += ws[j];
        float pk = (tp + EPSV) / Z;
        float pb = expf(blv - rm) / rs;
        float pi = (1.0f - LAM) * pb + LAM * pk;
        if ((long long)o < out_size)            out[o]          = logf(pi);
        if ((long long)(BV + o) < out_size)     out[BV + o]     = blv;
        if ((long long)(2 * BV + o) < out_size) out[2 * BV + o] = logf(tp + EPSV);
    };

    const int v4 = mis + (blockIdx.x * 256 + tid) * 4;
    if (v4 + 4 <= Vv) {
        const size_t off = rowoff + v4;
        if ((long long)(2 * BV + off + 4) <= out_size) {
            float4 blv = *(const float4*)(bl + off);
            float tp[4] = {0.f, 0.f, 0.f, 0.f};
            #pragma unroll
            for (int j = 0; j < Kk; ++j) {
                int d = ts[j] - v4;
                if ((unsigned)d < 4u) tp[d] += ws[j];
            }
            float bv[4] = {blv.x, blv.y, blv.z, blv.w};
            float4 o1, o3;
            float* o1p = &o1.x; float* o3p = &o3.x;
            #pragma unroll
            for (int cidx = 0; cidx < 4; ++cidx) {
                float pk = (tp[cidx] + EPSV) / Z;
                float pb = expf(bv[cidx] - rm) / rs;
                o1p[cidx] = logf((1.0f - LAM) * pb + LAM * pk);
                o3p[cidx] = logf(tp[cidx] + EPSV);
            }
            *(float4*)(out + off)          = o1;
            *(float4*)(out + BV + off)     = blv;
            *(float4*)(out + 2 * BV + off) = o3;
        } else {
            #pragma unroll
            for (int cidx = 0; cidx < 4; ++cidx) emit(v4 + cidx);
        }
    } else {
        for (int v = v4; v < Vv; ++v) emit(v);
    }
    if (blockIdx.x == 0 && tid < mis) emit(tid);
}

// =====================================================================
extern "C" void kernel_launch(void* const* d_in, const int* in_sizes, int n_in,
                              void* d_out, int out_size) {
    const float* qh   = (const float*)d_in[0];   // [B, D] f32
    const float* bl   = (const float*)d_in[1];   // [B, V] f32
    const float* keys = (const float*)d_in[2];   // [N, D] f32
    const void*  vals = d_in[3];                 // [N] int64 (or int32)
    float* out = (float*)d_out;

    cudaFuncSetAttribute(k_scores_f16, cudaFuncAttributeMaxDynamicSharedMemorySize, SMEM_BYTES);

    k_prepq<<<(Bq * Dd + 511) / 512, 512>>>(qh);
    k_dummy<<<1, 32>>>();                        // align ncu capture slot
    k_dummy<<<1, 32>>>();                        // (capture = 4th launch)
    k_scores_f16<<<NCHUNK, 256, SMEM_BYTES>>>(keys);
    k_topk<<<Bq, 256>>>(qh, keys, vals);
    k_rowstats_part<<<Bq * 4, 256>>>(bl);
    dim3 g3((Vv / 4 + 256) / 256, Bq);
    k_final<<<g3, 256>>>(bl, out, (long long)out_size);
}